// round 15
// baseline (speedup 1.0000x reference)
#include <cuda_runtime.h>
#include <cuda_fp16.h>
#include <math.h>
#include <stdint.h>

// Problem constants
#define L_DIM   2048
#define E_DIM   512
#define EPT_DIM 300
#define H_DIM   16
#define KBIG    (H_DIM * EPT_DIM)   // 4800

#define BANDW 1e-4f

// Scratch (allocation-free rule: __device__ globals)
__device__ __half g_Zh [L_DIM * KBIG];   // fp16 Z (zzt input)
__device__ float  g_inv[L_DIM * H_DIM];  // per-(l,h) 0.25/norm
__device__ float  g_S  [L_DIM * L_DIM];  // scores
__device__ __half g_Phi[L_DIM * L_DIM];  // adj fp16
__device__ __half g_Ah [L_DIM * E_DIM];  // Lemb / X1 fp16
__device__ __half g_Wt [2 * E_DIM * E_DIM]; // W0^T, W1^T fp16
__device__ __half g_Th [E_DIM * L_DIM];  // T^T fp16 (B operand of gcn)

// ===========================================================================
// Helpers
// ===========================================================================
__device__ __forceinline__ uint32_t smem_u32(const void* p) {
    uint32_t a;
    asm("{ .reg .u64 t; cvta.to.shared.u64 t, %1; cvt.u32.u64 %0, t; }"
        : "=r"(a) : "l"(p));
    return a;
}
__device__ __forceinline__ void ldsm_x4(uint32_t* r, uint32_t addr) {
    asm volatile("ldmatrix.sync.aligned.m8n8.x4.shared.b16 {%0,%1,%2,%3}, [%4];"
                 : "=r"(r[0]), "=r"(r[1]), "=r"(r[2]), "=r"(r[3]) : "r"(addr));
}
__device__ __forceinline__ void mma_f16(float* d, const uint32_t* a,
                                        const uint32_t* b) {
    asm volatile("mma.sync.aligned.m16n8k16.row.col.f32.f16.f16.f32 "
                 "{%0,%1,%2,%3}, {%4,%5,%6,%7}, {%8,%9}, {%0,%1,%2,%3};"
                 : "+f"(d[0]), "+f"(d[1]), "+f"(d[2]), "+f"(d[3])
                 : "r"(a[0]), "r"(a[1]), "r"(a[2]), "r"(a[3]),
                   "r"(b[0]), "r"(b[1]));
}
#define CP_ASYNC16(dst, src) \
    asm volatile("cp.async.cg.shared.global [%0], [%1], 16;" \
                 :: "r"(dst), "l"(src))
#define CP_COMMIT()  asm volatile("cp.async.commit_group;" ::: "memory")
#define CP_WAIT(N)   asm volatile("cp.async.wait_group " #N ";" ::: "memory")

// ===========================================================================
// Kernel 1: prep_all — compute_z + Lemb->fp16 + W0^T/W1^T->fp16, one launch.
// ===========================================================================
#define PREP_ZB   L_DIM              // 2048
#define PREP_LB   512
#define PREP_WB   256
#define PREP_GRID (PREP_ZB + PREP_LB + PREP_WB)

__global__ __launch_bounds__(512) void prep_all(
    const float* __restrict__ xpt, const float* __restrict__ Wpt,
    const float* __restrict__ Lemb,
    const float* __restrict__ W0, const float* __restrict__ W1,
    __half* __restrict__ Zh, float* __restrict__ invs,
    __half* __restrict__ Ah, __half* __restrict__ Wt)
{
    __shared__ float tbuf[2][32][33];
    const int blk = blockIdx.x;

    if (blk < PREP_ZB) {
        const int l    = blk;
        const int h    = threadIdx.x >> 5;
        const int lane = threadIdx.x & 31;
        const float* xrow = xpt + (size_t)l * EPT_DIM;
        const float* wrow = Wpt + h * EPT_DIM;

        float v0[5], v1[5];
        float ss = 0.f;
        #pragma unroll
        for (int i = 0; i < 5; i++) {
            int p = lane + i * 32;
            float a = 0.f, b = 0.f;
            if (p < EPT_DIM / 2) {
                int e = 2 * p;
                float w0 = wrow[e], w1 = wrow[e + 1];
                a = xrow[e] * w0 * w0;
                b = xrow[e + 1] * w1 * w1;
            }
            v0[i] = a; v1[i] = b;
            ss += a * a + b * b;
        }
        #pragma unroll
        for (int o = 16; o; o >>= 1) ss += __shfl_xor_sync(0xffffffffu, ss, o);
        float inv = 0.25f / fmaxf(sqrtf(ss), 1e-12f);
        if (lane == 0) invs[l * H_DIM + h] = inv;

        size_t base = (size_t)l * KBIG + h * EPT_DIM;
        #pragma unroll
        for (int i = 0; i < 5; i++) {
            int p = lane + i * 32;
            if (p < EPT_DIM / 2) {
                __half2 hv = __halves2half2(__float2half_rn(v0[i] * inv),
                                            __float2half_rn(v1[i] * inv));
                *(__half2*)(Zh + base + 2 * p) = hv;
            }
        }
    } else if (blk < PREP_ZB + PREP_LB) {
        int i4 = ((blk - PREP_ZB) * 512 + threadIdx.x) * 4;
        float4 v = *(const float4*)(Lemb + i4);
        __half2 h0 = __halves2half2(__float2half_rn(v.x), __float2half_rn(v.y));
        __half2 h1 = __halves2half2(__float2half_rn(v.z), __float2half_rn(v.w));
        *(__half2*)(Ah + i4)     = h0;
        *(__half2*)(Ah + i4 + 2) = h1;
    } else {
        int b    = blk - PREP_ZB - PREP_LB;
        int hf   = threadIdx.x >> 8;
        int t256 = threadIdx.x & 255;
        int tile = b * 2 + hf;
        int z    = tile >> 8;
        int rem  = tile & 255;
        int by   = (rem >> 4) * 32, bx = (rem & 15) * 32;
        const float* W = z ? W1 : W0;
        __half* wt = Wt + (size_t)z * E_DIM * E_DIM;
        const int x = t256 & 31, y4 = (t256 >> 5) * 4;
        #pragma unroll
        for (int i = 0; i < 4; i++)
            tbuf[hf][y4 + i][x] = W[(size_t)(by + y4 + i) * E_DIM + bx + x];
        __syncthreads();
        #pragma unroll
        for (int i = 0; i < 4; i++) {
            float v = tbuf[hf][x][y4 + i];
            wt[(size_t)(bx + y4 + i) * E_DIM + by + x] = __float2half_rn(v);
        }
    }
}

// ===========================================================================
// Kernel 2: ZZ^T single-pass fp16 mma.sync; 512 threads (16 warps, 4x4 grid,
// warp tile 32x32); pair-wise k-tiles, 3 pair-slots; symmetric.
// ===========================================================================
#define TILE_B   16384
#define STAGE_B  (2 * TILE_B)              // A+B tile-stage: 32 KB
#define PAIR_B   (2 * STAGE_B)             // pair-slot: 64 KB
#define ZZT_SMEM (3 * PAIR_B + 128)

__global__ void __launch_bounds__(512, 1) zzt_mma(
    const __half* __restrict__ Zh, float* __restrict__ S)
{
    const int bx = blockIdx.x, by = blockIdx.y;
    if (bx < by) return;
    extern __shared__ char smem_raw[];
    const uint32_t sb = (smem_u32(smem_raw) + 127u) & ~127u;

    const int tid  = threadIdx.x;
    const int wid  = tid >> 5, lane = tid & 31;
    const int bm = by << 7, bn = bx << 7;
    const int wm = wid >> 2, wn = wid & 3;     // 4 x 4 warp grid, 32x32 tile

    float acc[2][4][4];
    #pragma unroll
    for (int mt = 0; mt < 2; mt++)
        #pragma unroll
        for (int nt = 0; nt < 4; nt++)
            #pragma unroll
            for (int f = 0; f < 4; f++) acc[mt][nt][f] = 0.f;

    uint32_t offA[2][4], offBp[2][4];
    #pragma unroll
    for (int mt = 0; mt < 2; mt++) {
        int r  = wm * 32 + mt * 16 + (lane & 15);
        int r7 = r & 7;
        #pragma unroll
        for (int ks = 0; ks < 4; ks++) {
            int ch = ks * 2 + (lane >> 4);
            offA[mt][ks] = r * 128 + ((ch ^ r7) << 4);
        }
    }
    #pragma unroll
    for (int p = 0; p < 2; p++) {
        int ntl = p * 2 + ((lane >> 4) & 1);
        int r   = wn * 32 + ntl * 8 + (lane & 7);
        int r7  = r & 7;
        #pragma unroll
        for (int ks = 0; ks < 4; ks++) {
            int ch = ks * 2 + ((lane >> 3) & 1);
            offBp[p][ks] = r * 128 + ((ch ^ r7) << 4);
        }
    }

    // loaders: 1024 16B chunks per 16KB tile, 512 threads -> 2 per thread
    uint32_t dstoff[2];
    int      srcA[2], srcB[2];
    #pragma unroll
    for (int t = 0; t < 2; t++) {
        int idx = tid + t * 512;
        int r = idx >> 3, ch = idx & 7;
        dstoff[t] = (uint32_t)(r * 128 + ((ch ^ (r & 7)) << 4));
        srcA[t] = (bm + r) * KBIG + ch * 8;
        srcB[t] = (bn + r) * KBIG + ch * 8;
    }

    const int NKT   = KBIG / 64;     // 75
    const int NPAIR = (NKT + 1) / 2; // 38

    auto cp_tile = [&](uint32_t base, int kt) {
        const int k0 = kt << 6;
        #pragma unroll
        for (int t = 0; t < 2; t++) {
            CP_ASYNC16(base + dstoff[t],          Zh + srcA[t] + k0);
            CP_ASYNC16(base + TILE_B + dstoff[t], Zh + srcB[t] + k0);
        }
    };
    auto cp_pair = [&](int p) {
        uint32_t base = sb + (uint32_t)(p % 3) * PAIR_B;
        cp_tile(base, 2 * p);
        if (2 * p + 1 < NKT) cp_tile(base + STAGE_B, 2 * p + 1);
        CP_COMMIT();
    };

    auto compute = [&](uint32_t pa) {
        #pragma unroll
        for (int ks = 0; ks < 4; ks++) {
            uint32_t ah[2][4];
            #pragma unroll
            for (int mt = 0; mt < 2; mt++)
                ldsm_x4(ah[mt], pa + offA[mt][ks]);
            #pragma unroll
            for (int p = 0; p < 2; p++) {
                uint32_t bh[4];
                ldsm_x4(bh, pa + TILE_B + offBp[p][ks]);
                #pragma unroll
                for (int half = 0; half < 2; half++) {
                    int nt = p * 2 + half;
                    #pragma unroll
                    for (int mt = 0; mt < 2; mt++)
                        mma_f16(acc[mt][nt], ah[mt], bh + 2 * half);
                }
            }
        }
    };

    cp_pair(0);
    cp_pair(1);
    for (int p = 0; p < NPAIR; p++) {
        if (p + 1 < NPAIR) { CP_WAIT(1); } else { CP_WAIT(0); }
        __syncthreads();
        if (p + 2 < NPAIR) cp_pair(p + 2);
        uint32_t base = sb + (uint32_t)(p % 3) * PAIR_B;
        compute(base);
        if (2 * p + 1 < NKT) compute(base + STAGE_B);
    }

    #pragma unroll
    for (int mt = 0; mt < 2; mt++)
        #pragma unroll
        for (int nt = 0; nt < 4; nt++) {
            const int r0 = bm + wm * 32 + mt * 16 + (lane >> 2);
            const int c0 = bn + wn * 32 + nt * 8 + (lane & 3) * 2;
            const float* d = acc[mt][nt];
            *(float2*)(S + (size_t)r0 * L_DIM + c0)       = make_float2(d[0], d[1]);
            *(float2*)(S + (size_t)(r0 + 8) * L_DIM + c0) = make_float2(d[2], d[3]);
            if (bx != by) {
                S[(size_t)c0 * L_DIM + r0]           = d[0];
                S[(size_t)(c0 + 1) * L_DIM + r0]     = d[1];
                S[(size_t)c0 * L_DIM + r0 + 8]       = d[2];
                S[(size_t)(c0 + 1) * L_DIM + r0 + 8] = d[3];
            }
        }
}

// ===========================================================================
// Kernel 3: masked softmax with inline exact fixup of near-threshold entries.
// ===========================================================================
#define MAXROWBAND 32

__global__ __launch_bounds__(256) void masked_softmax_fix(
    const float* __restrict__ S,
    const float* __restrict__ xpt, const float* __restrict__ Wpt,
    const float* __restrict__ invs, __half* __restrict__ Phi)
{
    __shared__ float red[8];
    __shared__ int   bcols[MAXROWBAND];
    __shared__ int   bcnt;
    __shared__ float ivp[H_DIM];
    __shared__ float exact_val;

    const int r   = blockIdx.x;
    const int tid = threadIdx.x;
    const float* row = S + (size_t)r * L_DIM;

    float v[8];
    #pragma unroll
    for (int i = 0; i < 8; i++) v[i] = row[tid + i * 256];

    if (tid == 0) bcnt = 0;
    __syncthreads();
    #pragma unroll
    for (int i = 0; i < 8; i++) {
        if (fabsf(v[i] - 0.1f) < BANDW) {
            int p = atomicAdd(&bcnt, 1);
            if (p < MAXROWBAND) bcols[p] = tid + i * 256;
        }
    }
    __syncthreads();

    int nb = bcnt; if (nb > MAXROWBAND) nb = MAXROWBAND;
    for (int b = 0; b < nb; b++) {
        int c = bcols[b];
        if (tid < H_DIM)
            ivp[tid] = invs[r * H_DIM + tid] * invs[c * H_DIM + tid];
        __syncthreads();
        const float* xr = xpt + (size_t)r * EPT_DIM;
        const float* xc = xpt + (size_t)c * EPT_DIM;
        float part = 0.f;
        for (int g = tid; g < KBIG; g += 256) {
            int h = g / EPT_DIM;
            int e = g - h * EPT_DIM;
            float w = Wpt[g];
            float w2 = w * w;
            part = fmaf((xr[e] * w2) * ivp[h], xc[e] * w2, part);
        }
        #pragma unroll
        for (int o = 16; o; o >>= 1)
            part += __shfl_xor_sync(0xffffffffu, part, o);
        if ((tid & 31) == 0) red[tid >> 5] = part;
        __syncthreads();
        if (tid == 0)
            exact_val = red[0] + red[1] + red[2] + red[3] +
                        red[4] + red[5] + red[6] + red[7];
        __syncthreads();
        if (tid == (c & 255)) v[c >> 8] = exact_val;
        __syncthreads();
    }

    float m = -1e30f;
    #pragma unroll
    for (int i = 0; i < 8; i++)
        if (v[i] >= 0.1f) m = fmaxf(m, v[i]);
    #pragma unroll
    for (int o = 16; o; o >>= 1) m = fmaxf(m, __shfl_xor_sync(0xffffffffu, m, o));
    if ((tid & 31) == 0) red[tid >> 5] = m;
    __syncthreads();
    float M = fmaxf(fmaxf(fmaxf(red[0], red[1]), fmaxf(red[2], red[3])),
                    fmaxf(fmaxf(red[4], red[5]), fmaxf(red[6], red[7])));
    __syncthreads();

    float sum = 0.f;
    #pragma unroll
    for (int i = 0; i < 8; i++) {
        v[i] = (v[i] >= 0.1f) ? expf(v[i] - M) : 0.f;
        sum += v[i];
    }
    #pragma unroll
    for (int o = 16; o; o >>= 1) sum += __shfl_xor_sync(0xffffffffu, sum, o);
    if ((tid & 31) == 0) red[tid >> 5] = sum;
    __syncthreads();
    float T = red[0] + red[1] + red[2] + red[3] +
              red[4] + red[5] + red[6] + red[7];
    float inv = 1.f / T;

    #pragma unroll
    for (int i = 0; i < 8; i++)
        Phi[(size_t)r * L_DIM + tid + i * 256] = __float2half_rn(v[i] * inv);
}

// ===========================================================================
// mma1p: 1-pass fp16 GEMM, 512 threads (16 warps, 4x4 grid, warp tile 32x16),
// pair-wise k-tiles, 3 pair-slots.
// EPI 0: fp32 row-major + relu; EPI 1: fp16 row-major + relu;
// EPI 2: fp16 transposed [n][m], no relu.
// ===========================================================================
#define QA_B 16384
#define QB_B 8192
#define QSTAGE_B (QA_B + QB_B)             // 24 KB
#define QPAIR_B  (2 * QSTAGE_B)            // 48 KB
#define MMA_SMEM (3 * QPAIR_B + 128)

template <int KDIM, int EPI>
__global__ void __launch_bounds__(512, 1) mma1p(
    const __half* __restrict__ A, const __half* __restrict__ B,
    float* __restrict__ Cf, __half* __restrict__ Ch)
{
    extern __shared__ char smem_raw[];
    const uint32_t sb = (smem_u32(smem_raw) + 127u) & ~127u;

    const int tid  = threadIdx.x;
    const int wid  = tid >> 5, lane = tid & 31;
    const int bm = blockIdx.y << 7;
    const int bn = blockIdx.x << 6;
    const int wm = wid >> 2, wn = wid & 3;    // 4 x 4 grid, warp tile 32x16

    float acc[2][2][4];
    #pragma unroll
    for (int mt = 0; mt < 2; mt++)
        #pragma unroll
        for (int nt = 0; nt < 2; nt++)
            #pragma unroll
            for (int f = 0; f < 4; f++) acc[mt][nt][f] = 0.f;

    uint32_t offA[2][4], offB[4];
    #pragma unroll
    for (int mt = 0; mt < 2; mt++) {
        int r  = wm * 32 + mt * 16 + (lane & 15);
        int r7 = r & 7;
        #pragma unroll
        for (int ks = 0; ks < 4; ks++) {
            int ch = ks * 2 + (lane >> 4);
            offA[mt][ks] = r * 128 + ((ch ^ r7) << 4);
        }
    }
    {
        int ntl = (lane >> 4) & 1;
        int r   = wn * 16 + ntl * 8 + (lane & 7);
        int r7  = r & 7;
        #pragma unroll
        for (int ks = 0; ks < 4; ks++) {
            int ch = ks * 2 + ((lane >> 3) & 1);
            offB[ks] = r * 128 + ((ch ^ r7) << 4);
        }
    }

    // loaders: A 1024 chunks -> 2/thread; B 512 chunks -> 1/thread
    uint32_t dstA[2]; int srcA[2];
    #pragma unroll
    for (int t = 0; t < 2; t++) {
        int idx = tid + t * 512;
        int r = idx >> 3, ch = idx & 7;
        dstA[t] = (uint32_t)(r * 128 + ((ch ^ (r & 7)) << 4));
        srcA[t] = (bm + r) * KDIM + ch * 8;
    }
    uint32_t dstB0; int srcB0;
    {
        int r = tid >> 3, ch = tid & 7;
        dstB0 = (uint32_t)(r * 128 + ((ch ^ (r & 7)) << 4));
        srcB0 = (bn + r) * KDIM + ch * 8;
    }

    const int NKT   = KDIM / 64;
    const int NPAIR = NKT / 2;

    auto cp_tile = [&](uint32_t base, int kt) {
        const int k0 = kt << 6;
        #pragma unroll
        for (int t = 0; t < 2; t++)
            CP_ASYNC16(base + dstA[t], A + srcA[t] + k0);
        CP_ASYNC16(base + QA_B + dstB0, B + srcB0 + k0);
    };
    auto cp_pair = [&](int p) {
        uint32_t base = sb + (uint32_t)(p % 3) * QPAIR_B;
        cp_tile(base, 2 * p);
        cp_tile(base + QSTAGE_B, 2 * p + 1);
        CP_COMMIT();
    };

    auto compute = [&](uint32_t pa) {
        #pragma unroll
        for (int ks = 0; ks < 4; ks++) {
            uint32_t ah[2][4], bh[4];
            #pragma unroll
            for (int mt = 0; mt < 2; mt++)
                ldsm_x4(ah[mt], pa + offA[mt][ks]);
            ldsm_x4(bh, pa + QA_B + offB[ks]);
            #pragma unroll
            for (int nt = 0; nt < 2; nt++)
                #pragma unroll
                for (int mt = 0; mt < 2; mt++)
                    mma_f16(acc[mt][nt], ah[mt], bh + 2 * nt);
        }
    };

    cp_pair(0);
    if (NPAIR > 1) cp_pair(1);
    for (int p = 0; p < NPAIR; p++) {
        if (p + 1 < NPAIR) { CP_WAIT(1); } else { CP_WAIT(0); }
        __syncthreads();
        if (p + 2 < NPAIR) cp_pair(p + 2);
        uint32_t base = sb + (uint32_t)(p % 3) * QPAIR_B;
        compute(base);
        compute(base + QSTAGE_B);
    }

    #pragma unroll
    for (int mt = 0; mt < 2; mt++)
        #pragma unroll
        for (int nt = 0; nt < 2; nt++) {
            const int r0 = bm + wm * 32 + mt * 16 + (lane >> 2);
            const int c0 = bn + wn * 16 + nt * 8 + (lane & 3) * 2;
            const float* d = acc[mt][nt];
            if (EPI == 2) {
                #pragma unroll
                for (int f = 0; f < 4; f++) {
                    int rr = r0 + (f >> 1) * 8;
                    int cc = c0 + (f & 1);
                    Ch[(size_t)cc * L_DIM + rr] = __float2half_rn(d[f]);
                }
            } else {
                #pragma unroll
                for (int hrow = 0; hrow < 2; hrow++) {
                    float v0 = fmaxf(d[hrow * 2 + 0], 0.f);
                    float v1 = fmaxf(d[hrow * 2 + 1], 0.f);
                    int rr = r0 + hrow * 8;
                    if (EPI == 1) {
                        *(__half2*)(Ch + (size_t)rr * E_DIM + c0) =
                            __halves2half2(__float2half_rn(v0),
                                           __float2half_rn(v1));
                    } else {
                        *(float2*)(Cf + (size_t)rr * E_DIM + c0) =
                            make_float2(v0, v1);
                    }
                }
            }
        }
}

// ===========================================================================
// Launch
// ===========================================================================
extern "C" void kernel_launch(void* const* d_in, const int* in_sizes, int n_in,
                              void* d_out, int out_size)
{
    const float* Lemb = (const float*)d_in[0];
    const float* Xpt  = (const float*)d_in[1];
    const float* Wpt  = (const float*)d_in[2];
    const float* W0   = (const float*)d_in[3];
    const float* W1   = (const float*)d_in[4];
    float* out = (float*)d_out;

    float *S, *invs;
    __half *Zh, *Phi, *Ah, *Wt, *Th;
    cudaGetSymbolAddress((void**)&Zh,   g_Zh);
    cudaGetSymbolAddress((void**)&invs, g_inv);
    cudaGetSymbolAddress((void**)&S,    g_S);
    cudaGetSymbolAddress((void**)&Phi,  g_Phi);
    cudaGetSymbolAddress((void**)&Ah,   g_Ah);
    cudaGetSymbolAddress((void**)&Wt,   g_Wt);
    cudaGetSymbolAddress((void**)&Th,   g_Th);

    cudaFuncSetAttribute(zzt_mma, cudaFuncAttributeMaxDynamicSharedMemorySize,
                         ZZT_SMEM);
    cudaFuncSetAttribute(mma1p<E_DIM, 2>,
                         cudaFuncAttributeMaxDynamicSharedMemorySize, MMA_SMEM);
    cudaFuncSetAttribute(mma1p<L_DIM, 0>,
                         cudaFuncAttributeMaxDynamicSharedMemorySize, MMA_SMEM);
    cudaFuncSetAttribute(mma1p<L_DIM, 1>,
                         cudaFuncAttributeMaxDynamicSharedMemorySize, MMA_SMEM);

    const dim3 gcn_grid(E_DIM / 64, L_DIM / 128);

    // 1) prep: Zh + invs + Lemb fp16 + W^T fp16 (one launch)
    prep_all<<<PREP_GRID, 512>>>(Xpt, Wpt, Lemb, W0, W1, Zh, invs, Ah, Wt);

    // 2) scores = Z Z^T (single-pass fp16 mma), symmetric, 16 warps/CTA
    zzt_mma<<<dim3(16, 16), 512, ZZT_SMEM>>>(Zh, S);

    // 3) adj = softmax(threshold(scores)) with inline exact band fixup
    masked_softmax_fix<<<L_DIM, 256>>>(S, Xpt, Wpt, invs, Phi);

    // 4) T0t = (Lemb @ W0)^T fp16
    mma1p<E_DIM, 2><<<gcn_grid, 512, MMA_SMEM>>>(Ah, Wt, nullptr, Th);

    // 5) X1 = relu(adj @ T0) -> fp16 (overwrites Ah)
    mma1p<L_DIM, 1><<<gcn_grid, 512, MMA_SMEM>>>(Phi, Th, nullptr, Ah);

    // 6) T1t = (X1 @ W1)^T fp16
    mma1p<E_DIM, 2><<<gcn_grid, 512, MMA_SMEM>>>(
        Ah, Wt + (size_t)E_DIM * E_DIM, nullptr, Th);

    // 7) out = relu(adj @ T1) fp32
    mma1p<L_DIM, 0><<<gcn_grid, 512, MMA_SMEM>>>(Phi, Th, out, nullptr);
}

// round 16
// speedup vs baseline: 1.0317x; 1.0317x over previous
#include <cuda_runtime.h>
#include <cuda_fp16.h>
#include <math.h>
#include <stdint.h>

// Problem constants
#define L_DIM   2048
#define E_DIM   512
#define EPT_DIM 300
#define H_DIM   16
#define KBIG    (H_DIM * EPT_DIM)   // 4800

#define BANDW 1e-4f

// Scratch (allocation-free rule: __device__ globals)
__device__ __half g_Zh [L_DIM * KBIG];   // fp16 Z (zzt input)
__device__ float  g_inv[L_DIM * H_DIM];  // per-(l,h) 0.25/norm
__device__ float  g_S  [L_DIM * L_DIM];  // scores
__device__ __half g_Phi[L_DIM * L_DIM];  // adj fp16
__device__ __half g_Ah [L_DIM * E_DIM];  // Lemb / X1 fp16
__device__ __half g_Wt [2 * E_DIM * E_DIM]; // W0^T, W1^T fp16
__device__ __half g_Th [E_DIM * L_DIM];  // T^T fp16 (B operand of gcn)

// ===========================================================================
// Helpers
// ===========================================================================
__device__ __forceinline__ uint32_t smem_u32(const void* p) {
    uint32_t a;
    asm("{ .reg .u64 t; cvta.to.shared.u64 t, %1; cvt.u32.u64 %0, t; }"
        : "=r"(a) : "l"(p));
    return a;
}
__device__ __forceinline__ void ldsm_x4(uint32_t* r, uint32_t addr) {
    asm volatile("ldmatrix.sync.aligned.m8n8.x4.shared.b16 {%0,%1,%2,%3}, [%4];"
                 : "=r"(r[0]), "=r"(r[1]), "=r"(r[2]), "=r"(r[3]) : "r"(addr));
}
__device__ __forceinline__ void mma_f16(float* d, const uint32_t* a,
                                        const uint32_t* b) {
    asm volatile("mma.sync.aligned.m16n8k16.row.col.f32.f16.f16.f32 "
                 "{%0,%1,%2,%3}, {%4,%5,%6,%7}, {%8,%9}, {%0,%1,%2,%3};"
                 : "+f"(d[0]), "+f"(d[1]), "+f"(d[2]), "+f"(d[3])
                 : "r"(a[0]), "r"(a[1]), "r"(a[2]), "r"(a[3]),
                   "r"(b[0]), "r"(b[1]));
}
#define CP_ASYNC16(dst, src) \
    asm volatile("cp.async.cg.shared.global [%0], [%1], 16;" \
                 :: "r"(dst), "l"(src))
#define CP_COMMIT()  asm volatile("cp.async.commit_group;" ::: "memory")
#define CP_WAIT(N)   asm volatile("cp.async.wait_group " #N ";" ::: "memory")

// ===========================================================================
// Kernel 1: prep_all — compute_z + Lemb->fp16 + W0^T/W1^T->fp16, one launch.
// ===========================================================================
#define PREP_ZB   L_DIM              // 2048
#define PREP_LB   512
#define PREP_WB   256
#define PREP_GRID (PREP_ZB + PREP_LB + PREP_WB)

__global__ __launch_bounds__(512) void prep_all(
    const float* __restrict__ xpt, const float* __restrict__ Wpt,
    const float* __restrict__ Lemb,
    const float* __restrict__ W0, const float* __restrict__ W1,
    __half* __restrict__ Zh, float* __restrict__ invs,
    __half* __restrict__ Ah, __half* __restrict__ Wt)
{
    __shared__ float tbuf[2][32][33];
    const int blk = blockIdx.x;

    if (blk < PREP_ZB) {
        const int l    = blk;
        const int h    = threadIdx.x >> 5;
        const int lane = threadIdx.x & 31;
        const float* xrow = xpt + (size_t)l * EPT_DIM;
        const float* wrow = Wpt + h * EPT_DIM;

        float v0[5], v1[5];
        float ss = 0.f;
        #pragma unroll
        for (int i = 0; i < 5; i++) {
            int p = lane + i * 32;
            float a = 0.f, b = 0.f;
            if (p < EPT_DIM / 2) {
                int e = 2 * p;
                float w0 = wrow[e], w1 = wrow[e + 1];
                a = xrow[e] * w0 * w0;
                b = xrow[e + 1] * w1 * w1;
            }
            v0[i] = a; v1[i] = b;
            ss += a * a + b * b;
        }
        #pragma unroll
        for (int o = 16; o; o >>= 1) ss += __shfl_xor_sync(0xffffffffu, ss, o);
        float inv = 0.25f / fmaxf(sqrtf(ss), 1e-12f);
        if (lane == 0) invs[l * H_DIM + h] = inv;

        size_t base = (size_t)l * KBIG + h * EPT_DIM;
        #pragma unroll
        for (int i = 0; i < 5; i++) {
            int p = lane + i * 32;
            if (p < EPT_DIM / 2) {
                __half2 hv = __halves2half2(__float2half_rn(v0[i] * inv),
                                            __float2half_rn(v1[i] * inv));
                *(__half2*)(Zh + base + 2 * p) = hv;
            }
        }
    } else if (blk < PREP_ZB + PREP_LB) {
        int i4 = ((blk - PREP_ZB) * 512 + threadIdx.x) * 4;
        float4 v = *(const float4*)(Lemb + i4);
        __half2 h0 = __halves2half2(__float2half_rn(v.x), __float2half_rn(v.y));
        __half2 h1 = __halves2half2(__float2half_rn(v.z), __float2half_rn(v.w));
        *(__half2*)(Ah + i4)     = h0;
        *(__half2*)(Ah + i4 + 2) = h1;
    } else {
        int b    = blk - PREP_ZB - PREP_LB;
        int hf   = threadIdx.x >> 8;
        int t256 = threadIdx.x & 255;
        int tile = b * 2 + hf;
        int z    = tile >> 8;
        int rem  = tile & 255;
        int by   = (rem >> 4) * 32, bx = (rem & 15) * 32;
        const float* W = z ? W1 : W0;
        __half* wt = Wt + (size_t)z * E_DIM * E_DIM;
        const int x = t256 & 31, y4 = (t256 >> 5) * 4;
        #pragma unroll
        for (int i = 0; i < 4; i++)
            tbuf[hf][y4 + i][x] = W[(size_t)(by + y4 + i) * E_DIM + bx + x];
        __syncthreads();
        #pragma unroll
        for (int i = 0; i < 4; i++) {
            float v = tbuf[hf][x][y4 + i];
            wt[(size_t)(bx + y4 + i) * E_DIM + by + x] = __float2half_rn(v);
        }
    }
}

// ===========================================================================
// Kernel 2: ZZ^T single-pass fp16 mma.sync; 256 threads (8 warps, 2x4 grid,
// warp tile 64x32); pair-wise k-tiles, 3 pair-slots; symmetric.  (R14 champion)
// ===========================================================================
#define TILE_B   16384
#define STAGE_B  (2 * TILE_B)              // A+B tile-stage: 32 KB
#define PAIR_B   (2 * STAGE_B)             // pair-slot: 64 KB
#define ZZT_SMEM (3 * PAIR_B + 128)

__global__ void __launch_bounds__(256, 1) zzt_mma(
    const __half* __restrict__ Zh, float* __restrict__ S)
{
    const int bx = blockIdx.x, by = blockIdx.y;
    if (bx < by) return;
    extern __shared__ char smem_raw[];
    const uint32_t sb = (smem_u32(smem_raw) + 127u) & ~127u;

    const int tid  = threadIdx.x;
    const int wid  = tid >> 5, lane = tid & 31;
    const int bm = by << 7, bn = bx << 7;
    const int wm = wid >> 2, wn = wid & 3;

    float acc[4][4][4];
    #pragma unroll
    for (int mt = 0; mt < 4; mt++)
        #pragma unroll
        for (int nt = 0; nt < 4; nt++)
            #pragma unroll
            for (int f = 0; f < 4; f++) acc[mt][nt][f] = 0.f;

    uint32_t offA[4][4], offBp[2][4];
    #pragma unroll
    for (int mt = 0; mt < 4; mt++) {
        int r  = wm * 64 + mt * 16 + (lane & 15);
        int r7 = r & 7;
        #pragma unroll
        for (int ks = 0; ks < 4; ks++) {
            int ch = ks * 2 + (lane >> 4);
            offA[mt][ks] = r * 128 + ((ch ^ r7) << 4);
        }
    }
    #pragma unroll
    for (int p = 0; p < 2; p++) {
        int ntl = p * 2 + ((lane >> 4) & 1);
        int r   = wn * 32 + ntl * 8 + (lane & 7);
        int r7  = r & 7;
        #pragma unroll
        for (int ks = 0; ks < 4; ks++) {
            int ch = ks * 2 + ((lane >> 3) & 1);
            offBp[p][ks] = r * 128 + ((ch ^ r7) << 4);
        }
    }

    uint32_t dstoff[4];
    int      srcA[4], srcB[4];
    #pragma unroll
    for (int t = 0; t < 4; t++) {
        int idx = tid + t * 256;
        int r = idx >> 3, ch = idx & 7;
        dstoff[t] = (uint32_t)(r * 128 + ((ch ^ (r & 7)) << 4));
        srcA[t] = (bm + r) * KBIG + ch * 8;
        srcB[t] = (bn + r) * KBIG + ch * 8;
    }

    const int NKT   = KBIG / 64;     // 75
    const int NPAIR = (NKT + 1) / 2; // 38

    auto cp_tile = [&](uint32_t base, int kt) {
        const int k0 = kt << 6;
        #pragma unroll
        for (int t = 0; t < 4; t++) {
            CP_ASYNC16(base + dstoff[t],          Zh + srcA[t] + k0);
            CP_ASYNC16(base + TILE_B + dstoff[t], Zh + srcB[t] + k0);
        }
    };
    auto cp_pair = [&](int p) {
        uint32_t base = sb + (uint32_t)(p % 3) * PAIR_B;
        cp_tile(base, 2 * p);
        if (2 * p + 1 < NKT) cp_tile(base + STAGE_B, 2 * p + 1);
        CP_COMMIT();
    };

    auto compute = [&](uint32_t pa) {
        #pragma unroll
        for (int ks = 0; ks < 4; ks++) {
            uint32_t ah[4][4];
            #pragma unroll
            for (int mt = 0; mt < 4; mt++)
                ldsm_x4(ah[mt], pa + offA[mt][ks]);
            #pragma unroll
            for (int p = 0; p < 2; p++) {
                uint32_t bh[4];
                ldsm_x4(bh, pa + TILE_B + offBp[p][ks]);
                #pragma unroll
                for (int half = 0; half < 2; half++) {
                    int nt = p * 2 + half;
                    #pragma unroll
                    for (int mt = 0; mt < 4; mt++)
                        mma_f16(acc[mt][nt], ah[mt], bh + 2 * half);
                }
            }
        }
    };

    cp_pair(0);
    cp_pair(1);
    for (int p = 0; p < NPAIR; p++) {
        if (p + 1 < NPAIR) { CP_WAIT(1); } else { CP_WAIT(0); }
        __syncthreads();
        if (p + 2 < NPAIR) cp_pair(p + 2);
        uint32_t base = sb + (uint32_t)(p % 3) * PAIR_B;
        compute(base);
        if (2 * p + 1 < NKT) compute(base + STAGE_B);
    }

    #pragma unroll
    for (int mt = 0; mt < 4; mt++)
        #pragma unroll
        for (int nt = 0; nt < 4; nt++) {
            const int r0 = bm + wm * 64 + mt * 16 + (lane >> 2);
            const int c0 = bn + wn * 32 + nt * 8 + (lane & 3) * 2;
            const float* d = acc[mt][nt];
            *(float2*)(S + (size_t)r0 * L_DIM + c0)       = make_float2(d[0], d[1]);
            *(float2*)(S + (size_t)(r0 + 8) * L_DIM + c0) = make_float2(d[2], d[3]);
            if (bx != by) {
                S[(size_t)c0 * L_DIM + r0]           = d[0];
                S[(size_t)(c0 + 1) * L_DIM + r0]     = d[1];
                S[(size_t)c0 * L_DIM + r0 + 8]       = d[2];
                S[(size_t)(c0 + 1) * L_DIM + r0 + 8] = d[3];
            }
        }
}

// ===========================================================================
// Kernel 3: masked softmax with inline exact fixup of near-threshold entries.
// ===========================================================================
#define MAXROWBAND 32

__global__ __launch_bounds__(256) void masked_softmax_fix(
    const float* __restrict__ S,
    const float* __restrict__ xpt, const float* __restrict__ Wpt,
    const float* __restrict__ invs, __half* __restrict__ Phi)
{
    __shared__ float red[8];
    __shared__ int   bcols[MAXROWBAND];
    __shared__ int   bcnt;
    __shared__ float ivp[H_DIM];
    __shared__ float exact_val;

    const int r   = blockIdx.x;
    const int tid = threadIdx.x;
    const float* row = S + (size_t)r * L_DIM;

    float v[8];
    #pragma unroll
    for (int i = 0; i < 8; i++) v[i] = row[tid + i * 256];

    if (tid == 0) bcnt = 0;
    __syncthreads();
    #pragma unroll
    for (int i = 0; i < 8; i++) {
        if (fabsf(v[i] - 0.1f) < BANDW) {
            int p = atomicAdd(&bcnt, 1);
            if (p < MAXROWBAND) bcols[p] = tid + i * 256;
        }
    }
    __syncthreads();

    int nb = bcnt; if (nb > MAXROWBAND) nb = MAXROWBAND;
    for (int b = 0; b < nb; b++) {
        int c = bcols[b];
        if (tid < H_DIM)
            ivp[tid] = invs[r * H_DIM + tid] * invs[c * H_DIM + tid];
        __syncthreads();
        const float* xr = xpt + (size_t)r * EPT_DIM;
        const float* xc = xpt + (size_t)c * EPT_DIM;
        float part = 0.f;
        for (int g = tid; g < KBIG; g += 256) {
            int h = g / EPT_DIM;
            int e = g - h * EPT_DIM;
            float w = Wpt[g];
            float w2 = w * w;
            part = fmaf((xr[e] * w2) * ivp[h], xc[e] * w2, part);
        }
        #pragma unroll
        for (int o = 16; o; o >>= 1)
            part += __shfl_xor_sync(0xffffffffu, part, o);
        if ((tid & 31) == 0) red[tid >> 5] = part;
        __syncthreads();
        if (tid == 0)
            exact_val = red[0] + red[1] + red[2] + red[3] +
                        red[4] + red[5] + red[6] + red[7];
        __syncthreads();
        if (tid == (c & 255)) v[c >> 8] = exact_val;
        __syncthreads();
    }

    float m = -1e30f;
    #pragma unroll
    for (int i = 0; i < 8; i++)
        if (v[i] >= 0.1f) m = fmaxf(m, v[i]);
    #pragma unroll
    for (int o = 16; o; o >>= 1) m = fmaxf(m, __shfl_xor_sync(0xffffffffu, m, o));
    if ((tid & 31) == 0) red[tid >> 5] = m;
    __syncthreads();
    float M = fmaxf(fmaxf(fmaxf(red[0], red[1]), fmaxf(red[2], red[3])),
                    fmaxf(fmaxf(red[4], red[5]), fmaxf(red[6], red[7])));
    __syncthreads();

    float sum = 0.f;
    #pragma unroll
    for (int i = 0; i < 8; i++) {
        v[i] = (v[i] >= 0.1f) ? expf(v[i] - M) : 0.f;
        sum += v[i];
    }
    #pragma unroll
    for (int o = 16; o; o >>= 1) sum += __shfl_xor_sync(0xffffffffu, sum, o);
    if ((tid & 31) == 0) red[tid >> 5] = sum;
    __syncthreads();
    float T = red[0] + red[1] + red[2] + red[3] +
              red[4] + red[5] + red[6] + red[7];
    float inv = 1.f / T;

    #pragma unroll
    for (int i = 0; i < 8; i++)
        Phi[(size_t)r * L_DIM + tid + i * 256] = __float2half_rn(v[i] * inv);
}

// ===========================================================================
// mma1p: 1-pass fp16 GEMM, 64x64 CTA tile, 256 threads (8 warps, 2x4 grid,
// warp tile 32x16), pair-wise k-tiles, 3 pair-slots, 2 CTAs/SM.
// EPI 0: fp32 row-major + relu; EPI 1: fp16 row-major + relu;
// EPI 2: fp16 transposed [n][m], no relu.
// ===========================================================================
#define QA_B 8192                          // A tile: 64 x 128B
#define QB_B 8192                          // B tile: 64 x 128B
#define QSTAGE_B (QA_B + QB_B)             // 16 KB
#define QPAIR_B  (2 * QSTAGE_B)            // 32 KB
#define MMA_SMEM (3 * QPAIR_B)             // 96 KB (x2 CTAs = 192 KB/SM)

template <int KDIM, int EPI>
__global__ void __launch_bounds__(256, 2) mma1p(
    const __half* __restrict__ A, const __half* __restrict__ B,
    float* __restrict__ Cf, __half* __restrict__ Ch)
{
    extern __shared__ char smem_raw[];
    const uint32_t sb = smem_u32(smem_raw);   // 96KB dynamic alloc is 128-aligned

    const int tid  = threadIdx.x;
    const int wid  = tid >> 5, lane = tid & 31;
    const int bm = blockIdx.y << 6;
    const int bn = blockIdx.x << 6;
    const int wm = wid >> 2, wn = wid & 3;    // 2 x 4 grid, warp tile 32x16

    float acc[2][2][4];
    #pragma unroll
    for (int mt = 0; mt < 2; mt++)
        #pragma unroll
        for (int nt = 0; nt < 2; nt++)
            #pragma unroll
            for (int f = 0; f < 4; f++) acc[mt][nt][f] = 0.f;

    uint32_t offA[2][4], offB[4];
    #pragma unroll
    for (int mt = 0; mt < 2; mt++) {
        int r  = wm * 32 + mt * 16 + (lane & 15);
        int r7 = r & 7;
        #pragma unroll
        for (int ks = 0; ks < 4; ks++) {
            int ch = ks * 2 + (lane >> 4);
            offA[mt][ks] = r * 128 + ((ch ^ r7) << 4);
        }
    }
    {
        int ntl = (lane >> 4) & 1;
        int r   = wn * 16 + ntl * 8 + (lane & 7);
        int r7  = r & 7;
        #pragma unroll
        for (int ks = 0; ks < 4; ks++) {
            int ch = ks * 2 + ((lane >> 3) & 1);
            offB[ks] = r * 128 + ((ch ^ r7) << 4);
        }
    }

    // loaders: A 512 chunks, B 512 chunks; 256 threads -> 2 each
    uint32_t dstA[2]; int srcA[2];
    uint32_t dstB[2]; int srcB[2];
    #pragma unroll
    for (int t = 0; t < 2; t++) {
        int idx = tid + t * 256;
        int r = idx >> 3, ch = idx & 7;
        uint32_t d = (uint32_t)(r * 128 + ((ch ^ (r & 7)) << 4));
        dstA[t] = d;
        dstB[t] = d;
        srcA[t] = (bm + r) * KDIM + ch * 8;
        srcB[t] = (bn + r) * KDIM + ch * 8;
    }

    const int NKT   = KDIM / 64;
    const int NPAIR = NKT / 2;

    auto cp_tile = [&](uint32_t base, int kt) {
        const int k0 = kt << 6;
        #pragma unroll
        for (int t = 0; t < 2; t++) {
            CP_ASYNC16(base + dstA[t],        A + srcA[t] + k0);
            CP_ASYNC16(base + QA_B + dstB[t], B + srcB[t] + k0);
        }
    };
    auto cp_pair = [&](int p) {
        uint32_t base = sb + (uint32_t)(p % 3) * QPAIR_B;
        cp_tile(base, 2 * p);
        cp_tile(base + QSTAGE_B, 2 * p + 1);
        CP_COMMIT();
    };

    auto compute = [&](uint32_t pa) {
        #pragma unroll
        for (int ks = 0; ks < 4; ks++) {
            uint32_t ah[2][4], bh[4];
            #pragma unroll
            for (int mt = 0; mt < 2; mt++)
                ldsm_x4(ah[mt], pa + offA[mt][ks]);
            ldsm_x4(bh, pa + QA_B + offB[ks]);
            #pragma unroll
            for (int nt = 0; nt < 2; nt++)
                #pragma unroll
                for (int mt = 0; mt < 2; mt++)
                    mma_f16(acc[mt][nt], ah[mt], bh + 2 * nt);
        }
    };

    cp_pair(0);
    if (NPAIR > 1) cp_pair(1);
    for (int p = 0; p < NPAIR; p++) {
        if (p + 1 < NPAIR) { CP_WAIT(1); } else { CP_WAIT(0); }
        __syncthreads();
        if (p + 2 < NPAIR) cp_pair(p + 2);
        uint32_t base = sb + (uint32_t)(p % 3) * QPAIR_B;
        compute(base);
        compute(base + QSTAGE_B);
    }

    #pragma unroll
    for (int mt = 0; mt < 2; mt++)
        #pragma unroll
        for (int nt = 0; nt < 2; nt++) {
            const int r0 = bm + wm * 32 + mt * 16 + (lane >> 2);
            const int c0 = bn + wn * 16 + nt * 8 + (lane & 3) * 2;
            const float* d = acc[mt][nt];
            if (EPI == 2) {
                #pragma unroll
                for (int f = 0; f < 4; f++) {
                    int rr = r0 + (f >> 1) * 8;
                    int cc = c0 + (f & 1);
                    Ch[(size_t)cc * L_DIM + rr] = __float2half_rn(d[f]);
                }
            } else {
                #pragma unroll
                for (int hrow = 0; hrow < 2; hrow++) {
                    float v0 = fmaxf(d[hrow * 2 + 0], 0.f);
                    float v1 = fmaxf(d[hrow * 2 + 1], 0.f);
                    int rr = r0 + hrow * 8;
                    if (EPI == 1) {
                        *(__half2*)(Ch + (size_t)rr * E_DIM + c0) =
                            __halves2half2(__float2half_rn(v0),
                                           __float2half_rn(v1));
                    } else {
                        *(float2*)(Cf + (size_t)rr * E_DIM + c0) =
                            make_float2(v0, v1);
                    }
                }
            }
        }
}

// ===========================================================================
// Launch
// ===========================================================================
extern "C" void kernel_launch(void* const* d_in, const int* in_sizes, int n_in,
                              void* d_out, int out_size)
{
    const float* Lemb = (const float*)d_in[0];
    const float* Xpt  = (const float*)d_in[1];
    const float* Wpt  = (const float*)d_in[2];
    const float* W0   = (const float*)d_in[3];
    const float* W1   = (const float*)d_in[4];
    float* out = (float*)d_out;

    float *S, *invs;
    __half *Zh, *Phi, *Ah, *Wt, *Th;
    cudaGetSymbolAddress((void**)&Zh,   g_Zh);
    cudaGetSymbolAddress((void**)&invs, g_inv);
    cudaGetSymbolAddress((void**)&S,    g_S);
    cudaGetSymbolAddress((void**)&Phi,  g_Phi);
    cudaGetSymbolAddress((void**)&Ah,   g_Ah);
    cudaGetSymbolAddress((void**)&Wt,   g_Wt);
    cudaGetSymbolAddress((void**)&Th,   g_Th);

    cudaFuncSetAttribute(zzt_mma, cudaFuncAttributeMaxDynamicSharedMemorySize,
                         ZZT_SMEM);
    cudaFuncSetAttribute(mma1p<E_DIM, 2>,
                         cudaFuncAttributeMaxDynamicSharedMemorySize, MMA_SMEM);
    cudaFuncSetAttribute(mma1p<L_DIM, 0>,
                         cudaFuncAttributeMaxDynamicSharedMemorySize, MMA_SMEM);
    cudaFuncSetAttribute(mma1p<L_DIM, 1>,
                         cudaFuncAttributeMaxDynamicSharedMemorySize, MMA_SMEM);

    const dim3 gcn_grid(E_DIM / 64, L_DIM / 64);   // 8 x 32 = 256 CTAs

    // 1) prep: Zh + invs + Lemb fp16 + W^T fp16 (one launch)
    prep_all<<<PREP_GRID, 512>>>(Xpt, Wpt, Lemb, W0, W1, Zh, invs, Ah, Wt);

    // 2) scores = Z Z^T (single-pass fp16 mma), symmetric (R14 config)
    zzt_mma<<<dim3(16, 16), 256, ZZT_SMEM>>>(Zh, S);

    // 3) adj = softmax(threshold(scores)) with inline exact band fixup
    masked_softmax_fix<<<L_DIM, 256>>>(S, Xpt, Wpt, invs, Phi);

    // 4) T0t = (Lemb @ W0)^T fp16
    mma1p<E_DIM, 2><<<gcn_grid, 256, MMA_SMEM>>>(Ah, Wt, nullptr, Th);

    // 5) X1 = relu(adj @ T0) -> fp16 (overwrites Ah)
    mma1p<L_DIM, 1><<<gcn_grid, 256, MMA_SMEM>>>(Phi, Th, nullptr, Ah);

    // 6) T1t = (X1 @ W1)^T fp16
    mma1p<E_DIM, 2><<<gcn_grid, 256, MMA_SMEM>>>(
        Ah, Wt + (size_t)E_DIM * E_DIM, nullptr, Th);

    // 7) out = relu(adj @ T1) fp32
    mma1p<L_DIM, 0><<<gcn_grid, 256, MMA_SMEM>>>(Phi, Th, out, nullptr);
}

// round 17
// speedup vs baseline: 1.0922x; 1.0587x over previous
#include <cuda_runtime.h>
#include <cuda_fp16.h>
#include <math.h>
#include <stdint.h>

// Problem constants
#define L_DIM   2048
#define E_DIM   512
#define EPT_DIM 300
#define H_DIM   16
#define KBIG    (H_DIM * EPT_DIM)   // 4800

#define BANDW 1e-4f

// Scratch (allocation-free rule: __device__ globals)
__device__ __half g_Zh [L_DIM * KBIG];   // fp16 Z (zzt input)
__device__ float  g_inv[L_DIM * H_DIM];  // per-(l,h) 0.25/norm
__device__ float  g_S  [L_DIM * L_DIM];  // scores
__device__ __half g_Phi[L_DIM * L_DIM];  // adj fp16
__device__ __half g_Ah [L_DIM * E_DIM];  // Lemb / X1 fp16
__device__ __half g_Wt [2 * E_DIM * E_DIM]; // W0^T, W1^T fp16
__device__ __half g_Th [E_DIM * L_DIM];  // T^T fp16 (B operand of gcn)

// ===========================================================================
// Helpers
// ===========================================================================
__device__ __forceinline__ uint32_t smem_u32(const void* p) {
    uint32_t a;
    asm("{ .reg .u64 t; cvta.to.shared.u64 t, %1; cvt.u32.u64 %0, t; }"
        : "=r"(a) : "l"(p));
    return a;
}
__device__ __forceinline__ void ldsm_x4(uint32_t* r, uint32_t addr) {
    asm volatile("ldmatrix.sync.aligned.m8n8.x4.shared.b16 {%0,%1,%2,%3}, [%4];"
                 : "=r"(r[0]), "=r"(r[1]), "=r"(r[2]), "=r"(r[3]) : "r"(addr));
}
__device__ __forceinline__ void mma_f16(float* d, const uint32_t* a,
                                        const uint32_t* b) {
    asm volatile("mma.sync.aligned.m16n8k16.row.col.f32.f16.f16.f32 "
                 "{%0,%1,%2,%3}, {%4,%5,%6,%7}, {%8,%9}, {%0,%1,%2,%3};"
                 : "+f"(d[0]), "+f"(d[1]), "+f"(d[2]), "+f"(d[3])
                 : "r"(a[0]), "r"(a[1]), "r"(a[2]), "r"(a[3]),
                   "r"(b[0]), "r"(b[1]));
}
#define CP_ASYNC16(dst, src) \
    asm volatile("cp.async.cg.shared.global [%0], [%1], 16;" \
                 :: "r"(dst), "l"(src))
#define CP_COMMIT()  asm volatile("cp.async.commit_group;" ::: "memory")
#define CP_WAIT(N)   asm volatile("cp.async.wait_group " #N ";" ::: "memory")

// ===========================================================================
// Kernel 1: prep_all — compute_z + Lemb->fp16 + W0^T/W1^T->fp16, one launch.
// ===========================================================================
#define PREP_ZB   L_DIM              // 2048
#define PREP_LB   512
#define PREP_WB   256
#define PREP_GRID (PREP_ZB + PREP_LB + PREP_WB)

__global__ __launch_bounds__(512) void prep_all(
    const float* __restrict__ xpt, const float* __restrict__ Wpt,
    const float* __restrict__ Lemb,
    const float* __restrict__ W0, const float* __restrict__ W1,
    __half* __restrict__ Zh, float* __restrict__ invs,
    __half* __restrict__ Ah, __half* __restrict__ Wt)
{
    __shared__ float tbuf[2][32][33];
    const int blk = blockIdx.x;

    if (blk < PREP_ZB) {
        const int l    = blk;
        const int h    = threadIdx.x >> 5;
        const int lane = threadIdx.x & 31;
        const float* xrow = xpt + (size_t)l * EPT_DIM;
        const float* wrow = Wpt + h * EPT_DIM;

        float v0[5], v1[5];
        float ss = 0.f;
        #pragma unroll
        for (int i = 0; i < 5; i++) {
            int p = lane + i * 32;
            float a = 0.f, b = 0.f;
            if (p < EPT_DIM / 2) {
                int e = 2 * p;
                float w0 = wrow[e], w1 = wrow[e + 1];
                a = xrow[e] * w0 * w0;
                b = xrow[e + 1] * w1 * w1;
            }
            v0[i] = a; v1[i] = b;
            ss += a * a + b * b;
        }
        #pragma unroll
        for (int o = 16; o; o >>= 1) ss += __shfl_xor_sync(0xffffffffu, ss, o);
        float inv = 0.25f / fmaxf(sqrtf(ss), 1e-12f);
        if (lane == 0) invs[l * H_DIM + h] = inv;

        size_t base = (size_t)l * KBIG + h * EPT_DIM;
        #pragma unroll
        for (int i = 0; i < 5; i++) {
            int p = lane + i * 32;
            if (p < EPT_DIM / 2) {
                __half2 hv = __halves2half2(__float2half_rn(v0[i] * inv),
                                            __float2half_rn(v1[i] * inv));
                *(__half2*)(Zh + base + 2 * p) = hv;
            }
        }
    } else if (blk < PREP_ZB + PREP_LB) {
        int i4 = ((blk - PREP_ZB) * 512 + threadIdx.x) * 4;
        float4 v = *(const float4*)(Lemb + i4);
        __half2 h0 = __halves2half2(__float2half_rn(v.x), __float2half_rn(v.y));
        __half2 h1 = __halves2half2(__float2half_rn(v.z), __float2half_rn(v.w));
        *(__half2*)(Ah + i4)     = h0;
        *(__half2*)(Ah + i4 + 2) = h1;
    } else {
        int b    = blk - PREP_ZB - PREP_LB;
        int hf   = threadIdx.x >> 8;
        int t256 = threadIdx.x & 255;
        int tile = b * 2 + hf;
        int z    = tile >> 8;
        int rem  = tile & 255;
        int by   = (rem >> 4) * 32, bx = (rem & 15) * 32;
        const float* W = z ? W1 : W0;
        __half* wt = Wt + (size_t)z * E_DIM * E_DIM;
        const int x = t256 & 31, y4 = (t256 >> 5) * 4;
        #pragma unroll
        for (int i = 0; i < 4; i++)
            tbuf[hf][y4 + i][x] = W[(size_t)(by + y4 + i) * E_DIM + bx + x];
        __syncthreads();
        #pragma unroll
        for (int i = 0; i < 4; i++) {
            float v = tbuf[hf][x][y4 + i];
            wt[(size_t)(bx + y4 + i) * E_DIM + by + x] = __float2half_rn(v);
        }
    }
}

// ===========================================================================
// Kernel 2: FUSED zzt + T0t.
// 1D grid of 256 CTAs, 256 threads:
//   blocks [0,136):   zzt upper-triangle tile (R14 config: 8 warps, 64x32
//                     warp tile, pair-wise k-tiles, 3 pair-slots)
//   blocks [136,256): 120 T0t workers grid-striding over 128 tiles of
//                     Th = (Ah @ Wt0)^T (R14 mma1p K=512/EPI2 pipeline)
// ===========================================================================
#define TILE_B   16384
#define STAGE_B  (2 * TILE_B)              // zzt A+B tile-stage: 32 KB
#define PAIR_B   (2 * STAGE_B)             // zzt pair-slot: 64 KB
#define ZZT_SMEM (3 * PAIR_B + 128)        // 196736 B

// T0t pipeline (K=512): A tile 128x64, B tile 64x64
#define QA_B 16384
#define QB_B 8192
#define QSTAGE_B (QA_B + QB_B)             // 24 KB
#define QPAIR_B  (2 * QSTAGE_B)            // 48 KB (3 slots = 144 KB < 192)

__global__ void __launch_bounds__(256, 1) zzt_fused(
    const __half* __restrict__ Zh, float* __restrict__ S,
    const __half* __restrict__ Ah, const __half* __restrict__ Wt0,
    __half* __restrict__ Th)
{
    extern __shared__ char smem_raw[];
    const uint32_t sb = (smem_u32(smem_raw) + 127u) & ~127u;

    const int bid  = blockIdx.x;
    const int tid  = threadIdx.x;
    const int wid  = tid >> 5, lane = tid & 31;

    if (bid < 136) {
        // ---------------- zzt path (R14 champion, bm/bn from bid) ----------
        int by = 0, rem = bid;
        while (rem >= 16 - by) { rem -= 16 - by; by++; }
        const int bxi = by + rem;
        const int bm = by << 7, bn = bxi << 7;
        const int wm = wid >> 2, wn = wid & 3;

        float acc[4][4][4];
        #pragma unroll
        for (int mt = 0; mt < 4; mt++)
            #pragma unroll
            for (int nt = 0; nt < 4; nt++)
                #pragma unroll
                for (int f = 0; f < 4; f++) acc[mt][nt][f] = 0.f;

        uint32_t offA[4][4], offBp[2][4];
        #pragma unroll
        for (int mt = 0; mt < 4; mt++) {
            int r  = wm * 64 + mt * 16 + (lane & 15);
            int r7 = r & 7;
            #pragma unroll
            for (int ks = 0; ks < 4; ks++) {
                int ch = ks * 2 + (lane >> 4);
                offA[mt][ks] = r * 128 + ((ch ^ r7) << 4);
            }
        }
        #pragma unroll
        for (int p = 0; p < 2; p++) {
            int ntl = p * 2 + ((lane >> 4) & 1);
            int r   = wn * 32 + ntl * 8 + (lane & 7);
            int r7  = r & 7;
            #pragma unroll
            for (int ks = 0; ks < 4; ks++) {
                int ch = ks * 2 + ((lane >> 3) & 1);
                offBp[p][ks] = r * 128 + ((ch ^ r7) << 4);
            }
        }

        uint32_t dstoff[4];
        int      srcA[4], srcB[4];
        #pragma unroll
        for (int t = 0; t < 4; t++) {
            int idx = tid + t * 256;
            int r = idx >> 3, ch = idx & 7;
            dstoff[t] = (uint32_t)(r * 128 + ((ch ^ (r & 7)) << 4));
            srcA[t] = (bm + r) * KBIG + ch * 8;
            srcB[t] = (bn + r) * KBIG + ch * 8;
        }

        const int NKT   = KBIG / 64;     // 75
        const int NPAIR = (NKT + 1) / 2; // 38

        auto cp_tile = [&](uint32_t base, int kt) {
            const int k0 = kt << 6;
            #pragma unroll
            for (int t = 0; t < 4; t++) {
                CP_ASYNC16(base + dstoff[t],          Zh + srcA[t] + k0);
                CP_ASYNC16(base + TILE_B + dstoff[t], Zh + srcB[t] + k0);
            }
        };
        auto cp_pair = [&](int p) {
            uint32_t base = sb + (uint32_t)(p % 3) * PAIR_B;
            cp_tile(base, 2 * p);
            if (2 * p + 1 < NKT) cp_tile(base + STAGE_B, 2 * p + 1);
            CP_COMMIT();
        };

        auto compute = [&](uint32_t pa) {
            #pragma unroll
            for (int ks = 0; ks < 4; ks++) {
                uint32_t ah[4][4];
                #pragma unroll
                for (int mt = 0; mt < 4; mt++)
                    ldsm_x4(ah[mt], pa + offA[mt][ks]);
                #pragma unroll
                for (int p = 0; p < 2; p++) {
                    uint32_t bh[4];
                    ldsm_x4(bh, pa + TILE_B + offBp[p][ks]);
                    #pragma unroll
                    for (int half = 0; half < 2; half++) {
                        int nt = p * 2 + half;
                        #pragma unroll
                        for (int mt = 0; mt < 4; mt++)
                            mma_f16(acc[mt][nt], ah[mt], bh + 2 * half);
                    }
                }
            }
        };

        cp_pair(0);
        cp_pair(1);
        for (int p = 0; p < NPAIR; p++) {
            if (p + 1 < NPAIR) { CP_WAIT(1); } else { CP_WAIT(0); }
            __syncthreads();
            if (p + 2 < NPAIR) cp_pair(p + 2);
            uint32_t base = sb + (uint32_t)(p % 3) * PAIR_B;
            compute(base);
            if (2 * p + 1 < NKT) compute(base + STAGE_B);
        }

        #pragma unroll
        for (int mt = 0; mt < 4; mt++)
            #pragma unroll
            for (int nt = 0; nt < 4; nt++) {
                const int r0 = bm + wm * 64 + mt * 16 + (lane >> 2);
                const int c0 = bn + wn * 32 + nt * 8 + (lane & 3) * 2;
                const float* d = acc[mt][nt];
                *(float2*)(S + (size_t)r0 * L_DIM + c0) =
                    make_float2(d[0], d[1]);
                *(float2*)(S + (size_t)(r0 + 8) * L_DIM + c0) =
                    make_float2(d[2], d[3]);
                if (bxi != by) {
                    S[(size_t)c0 * L_DIM + r0]           = d[0];
                    S[(size_t)(c0 + 1) * L_DIM + r0]     = d[1];
                    S[(size_t)c0 * L_DIM + r0 + 8]       = d[2];
                    S[(size_t)(c0 + 1) * L_DIM + r0 + 8] = d[3];
                }
            }
    } else {
        // ---------------- T0t worker path (R14 mma1p K=512, EPI2) ----------
        const int w  = bid - 136;          // 0..119, tiles: w and w+120 (<128)
        const int wm = wid >> 2, wn = wid & 3;   // 2x4 grid, warp tile 64x16

        uint32_t offA[4][4], offB[4];
        #pragma unroll
        for (int mt = 0; mt < 4; mt++) {
            int r  = wm * 64 + mt * 16 + (lane & 15);
            int r7 = r & 7;
            #pragma unroll
            for (int ks = 0; ks < 4; ks++) {
                int ch = ks * 2 + (lane >> 4);
                offA[mt][ks] = r * 128 + ((ch ^ r7) << 4);
            }
        }
        {
            int ntl = (lane >> 4) & 1;
            int r   = wn * 16 + ntl * 8 + (lane & 7);
            int r7  = r & 7;
            #pragma unroll
            for (int ks = 0; ks < 4; ks++) {
                int ch = ks * 2 + ((lane >> 3) & 1);
                offB[ks] = r * 128 + ((ch ^ r7) << 4);
            }
        }

        for (int t = w; t < 128; t += 120) {
            const int bm = (t >> 3) << 7;   // 0..15 -> *128 (M over 2048)
            const int bn = (t & 7) << 6;    // 0..7  -> *64  (N over 512)

            float acc[4][2][4];
            #pragma unroll
            for (int mt = 0; mt < 4; mt++)
                #pragma unroll
                for (int nt = 0; nt < 2; nt++)
                    #pragma unroll
                    for (int f = 0; f < 4; f++) acc[mt][nt][f] = 0.f;

            uint32_t dstA[4]; int srcA[4];
            #pragma unroll
            for (int tt = 0; tt < 4; tt++) {
                int idx = tid + tt * 256;
                int r = idx >> 3, ch = idx & 7;
                dstA[tt] = (uint32_t)(r * 128 + ((ch ^ (r & 7)) << 4));
                srcA[tt] = (bm + r) * E_DIM + ch * 8;
            }
            uint32_t dstB[2]; int srcB[2];
            #pragma unroll
            for (int tt = 0; tt < 2; tt++) {
                int idx = tid + tt * 256;
                int r = idx >> 3, ch = idx & 7;
                dstB[tt] = (uint32_t)(r * 128 + ((ch ^ (r & 7)) << 4));
                srcB[tt] = (bn + r) * E_DIM + ch * 8;
            }

            const int NKT = E_DIM / 64;   // 8
            const int NP  = NKT / 2;      // 4

            auto cp_tileq = [&](uint32_t base, int kt) {
                const int k0 = kt << 6;
                #pragma unroll
                for (int tt = 0; tt < 4; tt++)
                    CP_ASYNC16(base + dstA[tt], Ah + srcA[tt] + k0);
                #pragma unroll
                for (int tt = 0; tt < 2; tt++)
                    CP_ASYNC16(base + QA_B + dstB[tt], Wt0 + srcB[tt] + k0);
            };
            auto cp_pairq = [&](int p) {
                uint32_t base = sb + (uint32_t)(p % 3) * QPAIR_B;
                cp_tileq(base, 2 * p);
                cp_tileq(base + QSTAGE_B, 2 * p + 1);
                CP_COMMIT();
            };
            auto computeq = [&](uint32_t pa) {
                #pragma unroll
                for (int ks = 0; ks < 4; ks++) {
                    uint32_t ah[4][4], bh[4];
                    #pragma unroll
                    for (int mt = 0; mt < 4; mt++)
                        ldsm_x4(ah[mt], pa + offA[mt][ks]);
                    ldsm_x4(bh, pa + QA_B + offB[ks]);
                    #pragma unroll
                    for (int nt = 0; nt < 2; nt++)
                        #pragma unroll
                        for (int mt = 0; mt < 4; mt++)
                            mma_f16(acc[mt][nt], ah[mt], bh + 2 * nt);
                }
            };

            cp_pairq(0);
            cp_pairq(1);
            for (int p = 0; p < NP; p++) {
                if (p + 1 < NP) { CP_WAIT(1); } else { CP_WAIT(0); }
                __syncthreads();
                if (p + 2 < NP) cp_pairq(p + 2);
                uint32_t base = sb + (uint32_t)(p % 3) * QPAIR_B;
                computeq(base);
                computeq(base + QSTAGE_B);
            }

            // transposed fp16 epilogue: Th[n][m]
            #pragma unroll
            for (int mt = 0; mt < 4; mt++)
                #pragma unroll
                for (int nt = 0; nt < 2; nt++) {
                    const int r0 = bm + wm * 64 + mt * 16 + (lane >> 2);
                    const int c0 = bn + wn * 16 + nt * 8 + (lane & 3) * 2;
                    const float* d = acc[mt][nt];
                    #pragma unroll
                    for (int f = 0; f < 4; f++) {
                        int rr = r0 + (f >> 1) * 8;
                        int cc = c0 + (f & 1);
                        Th[(size_t)cc * L_DIM + rr] = __float2half_rn(d[f]);
                    }
                }
            __syncthreads();    // smem reuse barrier before next tile
        }
    }
}

// ===========================================================================
// Kernel 3: masked softmax with inline exact fixup of near-threshold entries.
// ===========================================================================
#define MAXROWBAND 32

__global__ __launch_bounds__(256) void masked_softmax_fix(
    const float* __restrict__ S,
    const float* __restrict__ xpt, const float* __restrict__ Wpt,
    const float* __restrict__ invs, __half* __restrict__ Phi)
{
    __shared__ float red[8];
    __shared__ int   bcols[MAXROWBAND];
    __shared__ int   bcnt;
    __shared__ float ivp[H_DIM];
    __shared__ float exact_val;

    const int r   = blockIdx.x;
    const int tid = threadIdx.x;
    const float* row = S + (size_t)r * L_DIM;

    float v[8];
    #pragma unroll
    for (int i = 0; i < 8; i++) v[i] = row[tid + i * 256];

    if (tid == 0) bcnt = 0;
    __syncthreads();
    #pragma unroll
    for (int i = 0; i < 8; i++) {
        if (fabsf(v[i] - 0.1f) < BANDW) {
            int p = atomicAdd(&bcnt, 1);
            if (p < MAXROWBAND) bcols[p] = tid + i * 256;
        }
    }
    __syncthreads();

    int nb = bcnt; if (nb > MAXROWBAND) nb = MAXROWBAND;
    for (int b = 0; b < nb; b++) {
        int c = bcols[b];
        if (tid < H_DIM)
            ivp[tid] = invs[r * H_DIM + tid] * invs[c * H_DIM + tid];
        __syncthreads();
        const float* xr = xpt + (size_t)r * EPT_DIM;
        const float* xc = xpt + (size_t)c * EPT_DIM;
        float part = 0.f;
        for (int g = tid; g < KBIG; g += 256) {
            int h = g / EPT_DIM;
            int e = g - h * EPT_DIM;
            float w = Wpt[g];
            float w2 = w * w;
            part = fmaf((xr[e] * w2) * ivp[h], xc[e] * w2, part);
        }
        #pragma unroll
        for (int o = 16; o; o >>= 1)
            part += __shfl_xor_sync(0xffffffffu, part, o);
        if ((tid & 31) == 0) red[tid >> 5] = part;
        __syncthreads();
        if (tid == 0)
            exact_val = red[0] + red[1] + red[2] + red[3] +
                        red[4] + red[5] + red[6] + red[7];
        __syncthreads();
        if (tid == (c & 255)) v[c >> 8] = exact_val;
        __syncthreads();
    }

    float m = -1e30f;
    #pragma unroll
    for (int i = 0; i < 8; i++)
        if (v[i] >= 0.1f) m = fmaxf(m, v[i]);
    #pragma unroll
    for (int o = 16; o; o >>= 1) m = fmaxf(m, __shfl_xor_sync(0xffffffffu, m, o));
    if ((tid & 31) == 0) red[tid >> 5] = m;
    __syncthreads();
    float M = fmaxf(fmaxf(fmaxf(red[0], red[1]), fmaxf(red[2], red[3])),
                    fmaxf(fmaxf(red[4], red[5]), fmaxf(red[6], red[7])));
    __syncthreads();

    float sum = 0.f;
    #pragma unroll
    for (int i = 0; i < 8; i++) {
        v[i] = (v[i] >= 0.1f) ? expf(v[i] - M) : 0.f;
        sum += v[i];
    }
    #pragma unroll
    for (int o = 16; o; o >>= 1) sum += __shfl_xor_sync(0xffffffffu, sum, o);
    if ((tid & 31) == 0) red[tid >> 5] = sum;
    __syncthreads();
    float T = red[0] + red[1] + red[2] + red[3] +
              red[4] + red[5] + red[6] + red[7];
    float inv = 1.f / T;

    #pragma unroll
    for (int i = 0; i < 8; i++)
        Phi[(size_t)r * L_DIM + tid + i * 256] = __float2half_rn(v[i] * inv);
}

// ===========================================================================
// mma1p: 1-pass fp16 GEMM (R14 config: 128x64 tile, 256 threads, pair-wise
// k-tiles, 3 pair-slots).
// EPI 0: fp32 row-major + relu; EPI 1: fp16 row-major + relu;
// EPI 2: fp16 transposed [n][m], no relu.
// ===========================================================================
#define MMA_SMEM (3 * QPAIR_B + 128)

template <int KDIM, int EPI>
__global__ void __launch_bounds__(256, 1) mma1p(
    const __half* __restrict__ A, const __half* __restrict__ B,
    float* __restrict__ Cf, __half* __restrict__ Ch)
{
    extern __shared__ char smem_raw[];
    const uint32_t sb = (smem_u32(smem_raw) + 127u) & ~127u;

    const int tid  = threadIdx.x;
    const int wid  = tid >> 5, lane = tid & 31;
    const int bm = blockIdx.y << 7;
    const int bn = blockIdx.x << 6;
    const int wm = wid >> 2, wn = wid & 3;

    float acc[4][2][4];
    #pragma unroll
    for (int mt = 0; mt < 4; mt++)
        #pragma unroll
        for (int nt = 0; nt < 2; nt++)
            #pragma unroll
            for (int f = 0; f < 4; f++) acc[mt][nt][f] = 0.f;

    uint32_t offA[4][4], offB[4];
    #pragma unroll
    for (int mt = 0; mt < 4; mt++) {
        int r  = wm * 64 + mt * 16 + (lane & 15);
        int r7 = r & 7;
        #pragma unroll
        for (int ks = 0; ks < 4; ks++) {
            int ch = ks * 2 + (lane >> 4);
            offA[mt][ks] = r * 128 + ((ch ^ r7) << 4);
        }
    }
    {
        int ntl = (lane >> 4) & 1;
        int r   = wn * 16 + ntl * 8 + (lane & 7);
        int r7  = r & 7;
        #pragma unroll
        for (int ks = 0; ks < 4; ks++) {
            int ch = ks * 2 + ((lane >> 3) & 1);
            offB[ks] = r * 128 + ((ch ^ r7) << 4);
        }
    }

    uint32_t dstA[4]; int srcA[4];
    #pragma unroll
    for (int t = 0; t < 4; t++) {
        int idx = tid + t * 256;
        int r = idx >> 3, ch = idx & 7;
        dstA[t] = (uint32_t)(r * 128 + ((ch ^ (r & 7)) << 4));
        srcA[t] = (bm + r) * KDIM + ch * 8;
    }
    uint32_t dstB[2]; int srcB[2];
    #pragma unroll
    for (int t = 0; t < 2; t++) {
        int idx = tid + t * 256;
        int r = idx >> 3, ch = idx & 7;
        dstB[t] = (uint32_t)(r * 128 + ((ch ^ (r & 7)) << 4));
        srcB[t] = (bn + r) * KDIM + ch * 8;
    }

    const int NKT   = KDIM / 64;
    const int NPAIR = NKT / 2;

    auto cp_tile = [&](uint32_t base, int kt) {
        const int k0 = kt << 6;
        #pragma unroll
        for (int t = 0; t < 4; t++)
            CP_ASYNC16(base + dstA[t], A + srcA[t] + k0);
        #pragma unroll
        for (int t = 0; t < 2; t++)
            CP_ASYNC16(base + QA_B + dstB[t], B + srcB[t] + k0);
    };
    auto cp_pair = [&](int p) {
        uint32_t base = sb + (uint32_t)(p % 3) * QPAIR_B;
        cp_tile(base, 2 * p);
        cp_tile(base + QSTAGE_B, 2 * p + 1);
        CP_COMMIT();
    };

    auto compute = [&](uint32_t pa) {
        #pragma unroll
        for (int ks = 0; ks < 4; ks++) {
            uint32_t ah[4][4], bh[4];
            #pragma unroll
            for (int mt = 0; mt < 4; mt++)
                ldsm_x4(ah[mt], pa + offA[mt][ks]);
            ldsm_x4(bh, pa + QA_B + offB[ks]);
            #pragma unroll
            for (int nt = 0; nt < 2; nt++)
                #pragma unroll
                for (int mt = 0; mt < 4; mt++)
                    mma_f16(acc[mt][nt], ah[mt], bh + 2 * nt);
        }
    };

    cp_pair(0);
    if (NPAIR > 1) cp_pair(1);
    for (int p = 0; p < NPAIR; p++) {
        if (p + 1 < NPAIR) { CP_WAIT(1); } else { CP_WAIT(0); }
        __syncthreads();
        if (p + 2 < NPAIR) cp_pair(p + 2);
        uint32_t base = sb + (uint32_t)(p % 3) * QPAIR_B;
        compute(base);
        compute(base + QSTAGE_B);
    }

    #pragma unroll
    for (int mt = 0; mt < 4; mt++)
        #pragma unroll
        for (int nt = 0; nt < 2; nt++) {
            const int r0 = bm + wm * 64 + mt * 16 + (lane >> 2);
            const int c0 = bn + wn * 16 + nt * 8 + (lane & 3) * 2;
            const float* d = acc[mt][nt];
            if (EPI == 2) {
                #pragma unroll
                for (int f = 0; f < 4; f++) {
                    int rr = r0 + (f >> 1) * 8;
                    int cc = c0 + (f & 1);
                    Ch[(size_t)cc * L_DIM + rr] = __float2half_rn(d[f]);
                }
            } else {
                #pragma unroll
                for (int hrow = 0; hrow < 2; hrow++) {
                    float v0 = fmaxf(d[hrow * 2 + 0], 0.f);
                    float v1 = fmaxf(d[hrow * 2 + 1], 0.f);
                    int rr = r0 + hrow * 8;
                    if (EPI == 1) {
                        *(__half2*)(Ch + (size_t)rr * E_DIM + c0) =
                            __halves2half2(__float2half_rn(v0),
                                           __float2half_rn(v1));
                    } else {
                        *(float2*)(Cf + (size_t)rr * E_DIM + c0) =
                            make_float2(v0, v1);
                    }
                }
            }
        }
}

// ===========================================================================
// Launch
// ===========================================================================
extern "C" void kernel_launch(void* const* d_in, const int* in_sizes, int n_in,
                              void* d_out, int out_size)
{
    const float* Lemb = (const float*)d_in[0];
    const float* Xpt  = (const float*)d_in[1];
    const float* Wpt  = (const float*)d_in[2];
    const float* W0   = (const float*)d_in[3];
    const float* W1   = (const float*)d_in[4];
    float* out = (float*)d_out;

    float *S, *invs;
    __half *Zh, *Phi, *Ah, *Wt, *Th;
    cudaGetSymbolAddress((void**)&Zh,   g_Zh);
    cudaGetSymbolAddress((void**)&invs, g_inv);
    cudaGetSymbolAddress((void**)&S,    g_S);
    cudaGetSymbolAddress((void**)&Phi,  g_Phi);
    cudaGetSymbolAddress((void**)&Ah,   g_Ah);
    cudaGetSymbolAddress((void**)&Wt,   g_Wt);
    cudaGetSymbolAddress((void**)&Th,   g_Th);

    cudaFuncSetAttribute(zzt_fused, cudaFuncAttributeMaxDynamicSharedMemorySize,
                         ZZT_SMEM);
    cudaFuncSetAttribute(mma1p<E_DIM, 2>,
                         cudaFuncAttributeMaxDynamicSharedMemorySize, MMA_SMEM);
    cudaFuncSetAttribute(mma1p<L_DIM, 0>,
                         cudaFuncAttributeMaxDynamicSharedMemorySize, MMA_SMEM);
    cudaFuncSetAttribute(mma1p<L_DIM, 1>,
                         cudaFuncAttributeMaxDynamicSharedMemorySize, MMA_SMEM);

    const dim3 gcn_grid(E_DIM / 64, L_DIM / 128);

    // 1) prep: Zh + invs + Lemb fp16 + W^T fp16 (one launch)
    prep_all<<<PREP_GRID, 512>>>(Xpt, Wpt, Lemb, W0, W1, Zh, invs, Ah, Wt);

    // 2) FUSED: scores = Z Z^T (136 CTAs) + T0t = (Lemb @ W0)^T (120 workers)
    zzt_fused<<<256, 256, ZZT_SMEM>>>(Zh, S, Ah, Wt, Th);

    // 3) adj = softmax(threshold(scores)) with inline exact band fixup
    masked_softmax_fix<<<L_DIM, 256>>>(S, Xpt, Wpt, invs, Phi);

    // 4) X1 = relu(adj @ T0) -> fp16 (overwrites Ah)
    mma1p<L_DIM, 1><<<gcn_grid, 256, MMA_SMEM>>>(Phi, Th, nullptr, Ah);

    // 5) T1t = (X1 @ W1)^T fp16
    mma1p<E_DIM, 2><<<gcn_grid, 256, MMA_SMEM>>>(
        Ah, Wt + (size_t)E_DIM * E_DIM, nullptr, Th);

    // 6) out = relu(adj @ T1) fp32
    mma1p<L_DIM, 0><<<gcn_grid, 256, MMA_SMEM>>>(Phi, Th, out, nullptr);
}